// round 16
// baseline (speedup 1.0000x reference)
#include <cuda_runtime.h>
#include <math.h>
#include <stdint.h>

#define KCODES 1024
#define DDIM   64
#define NBLOCKS 512       // 32768 rows / 64 rows per block
#define CTILES  16        // 1024 codes / 64 codes per tile

// B smem layout: quad [hi_k, hi_k+4, lo_k, lo_k+4] at Es[code*176 + kkGlobal*20 + t4*4]
#define KKSTRIDE 20
#define CSTRIDE  176

// dynamic smem layout (float offsets)
#define ES_OFF    0        // 64*176 = 11264
#define P_OFF     11264    // 4 pairs * 2 slots * 2 roles * 32 lanes * 2 floats = 1024
#define EN_OFF    12288    // 64
#define RM_OFF    12352    // 64
#define RZ_OFF    12416
#define RS_OFF    12480
#define RI_OFF    12544
#define IDX_OFF   12608
#define SCR_OFF   12672    // 256
#define FLG_OFF   12928
#define SMEM_FLOATS 12932
#define SMEM_BYTES  (SMEM_FLOATS * 4)

// ---------------- device scratch (no allocation allowed) ----------------
// g_hist, g_gram, g_done rely on the zero-invariant: zero at module load,
// re-zeroed by finalize at the end of every run (graph-replay safe).
__device__ float g_en2[KCODES];
__device__ int   g_hist[KCODES];
__device__ float g_usedp[16];
__device__ float g_pcommit[NBLOCKS];
__device__ float g_pent[NBLOCKS];
__device__ float g_gram[4096];
__device__ int   g_done;

// ---------------- helpers ----------------
__device__ __forceinline__ float to_tf32(float v) {
    float r;
    asm("cvt.rna.tf32.f32 %0, %1;" : "=f"(r) : "f"(v));
    return r;
}

__device__ __forceinline__ void mma_tf32(float& d0, float& d1, float& d2, float& d3,
                                         const uint32_t a[4], uint32_t b0, uint32_t b1) {
    asm("mma.sync.aligned.m16n8k8.row.col.f32.tf32.tf32.f32 "
        "{%0,%1,%2,%3}, {%4,%5,%6,%7}, {%8,%9}, {%0,%1,%2,%3};"
        : "+f"(d0), "+f"(d1), "+f"(d2), "+f"(d3)
        : "r"(a[0]), "r"(a[1]), "r"(a[2]), "r"(a[3]), "r"(b0), "r"(b1));
}

#define UPD2(mv, Zv, Sv, biv, av0, av1, col0) do {                            \
    float _q = fmaxf((av0), (av1));                                           \
    if (_q > (mv)) {                                                          \
        float _scl = __expf((mv) - _q);                                       \
        (Zv) *= _scl; (Sv) *= _scl;                                           \
        (mv) = _q;                                                            \
        (biv) = ((av0) >= (av1)) ? (col0) : (col0) + 1;                       \
    }                                                                         \
    float _p0 = __expf((av0) - (mv));                                         \
    float _p1 = __expf((av1) - (mv));                                         \
    (Zv) += _p0 + _p1;                                                        \
    (Sv) = fmaf((av0), _p0, fmaf((av1), _p1, (Sv)));                          \
} while (0)

#define MERGE(mv, Zv, Sv, biv, m2, Z2, S2, b2) do {                           \
    float _mm = fmaxf((mv), (m2));                                            \
    float _sA = __expf((mv) - _mm);                                           \
    float _sB = __expf((m2) - _mm);                                           \
    float _Zn = (Zv) * _sA + (Z2) * _sB;                                      \
    float _Sn = (Sv) * _sA + (S2) * _sB;                                      \
    if ((m2) > (mv) || ((m2) == (mv) && (b2) < (biv))) (biv) = (b2);          \
    (mv) = _mm; (Zv) = _Zn; (Sv) = _Sn; } while (0)

// ---------------- aux: en2 + used + ortho Gram partial (16 blocks x 256) ----------------
__global__ __launch_bounds__(256, 4)
void aux_kernel(const float* __restrict__ emb, const float* __restrict__ cc) {
    __shared__ float nt[64 * 68];
    __shared__ float scl[64];
    int tid = threadIdx.x;
    int k0 = blockIdx.x * 64;

#pragma unroll
    for (int i = 0; i < 4; i++) {
        int v = tid + 256 * i;
        int k = v >> 4, c4 = v & 15;
        *(float4*)(nt + k * 68 + c4 * 4) = ((const float4*)emb)[(size_t)(k0 + k) * 16 + c4];
    }
    __syncthreads();

    if (tid < 64) {
        float s = 0.f;
        const float* r = nt + tid * 68;
#pragma unroll 8
        for (int d = 0; d < 64; d++) s = fmaf(r[d], r[d], s);
        g_en2[k0 + tid] = s;
        float msk = (cc[k0 + tid] >= 1.f) ? 1.f : 0.f;
        scl[tid] = msk / fmaxf(sqrtf(s), 1e-12f);
    }
    __syncthreads();

    if (tid == 0) {
        float u = 0.f;
        for (int i = 0; i < 64; i++) u += (scl[i] > 0.f) ? 1.f : 0.f;
        g_usedp[blockIdx.x] = u;
    }

#pragma unroll
    for (int i = 0; i < 4; i++) {
        int v = tid + 256 * i;
        int k = v >> 4, c4 = v & 15;
        float4* p = (float4*)(nt + k * 68 + c4 * 4);
        float4 t = *p;
        float s = scl[k];
        t.x *= s; t.y *= s; t.z *= s; t.w *= s;
        *p = t;
    }
    __syncthreads();

    int a = tid >> 2;
    int bg = tid & 3;
    float acc[16];
#pragma unroll
    for (int i = 0; i < 16; i++) acc[i] = 0.f;
#pragma unroll 4
    for (int k = 0; k < 64; k++) {
        float va = nt[k * 68 + a];
        const float4* bp = (const float4*)(nt + k * 68 + bg * 16);
        float4 q0 = bp[0], q1 = bp[1], q2 = bp[2], q3 = bp[3];
        acc[0]  = fmaf(va, q0.x, acc[0]);  acc[1]  = fmaf(va, q0.y, acc[1]);
        acc[2]  = fmaf(va, q0.z, acc[2]);  acc[3]  = fmaf(va, q0.w, acc[3]);
        acc[4]  = fmaf(va, q1.x, acc[4]);  acc[5]  = fmaf(va, q1.y, acc[5]);
        acc[6]  = fmaf(va, q1.z, acc[6]);  acc[7]  = fmaf(va, q1.w, acc[7]);
        acc[8]  = fmaf(va, q2.x, acc[8]);  acc[9]  = fmaf(va, q2.y, acc[9]);
        acc[10] = fmaf(va, q2.z, acc[10]); acc[11] = fmaf(va, q2.w, acc[11]);
        acc[12] = fmaf(va, q3.x, acc[12]); acc[13] = fmaf(va, q3.y, acc[13]);
        acc[14] = fmaf(va, q3.z, acc[14]); acc[15] = fmaf(va, q3.w, acc[15]);
    }
    float* op = g_gram + a * 64 + bg * 16;
#pragma unroll
    for (int i = 0; i < 16; i++) atomicAdd(op + i, acc[i]);
}

// ---------------- main: warp-pair K-split tf32 3-term GEMM, 3 CTAs/SM ----------------
// Warps w (pair=w&3, role=w>>2): same 16 rows (pair*16..+15), K halves (role*32..+31).
// Partial dots exchanged via smem + per-pair named barrier; role0 finishes row g,
// role1 finishes row g+8.
__global__ __launch_bounds__(256, 3)
void main_kernel(const float* __restrict__ x, const float* __restrict__ emb,
                 float* __restrict__ out, int N) {
    extern __shared__ float sm[];
    float* Es     = sm + ES_OFF;
    float* P      = sm + P_OFF;
    float* en2s   = sm + EN_OFF;
    float* Rm     = sm + RM_OFF;
    float* Rz     = sm + RZ_OFF;
    float* Rs     = sm + RS_OFF;
    int*   RiA    = (int*)(sm + RI_OFF);
    int*   idxRow = (int*)(sm + IDX_OFF);
    float* scr    = sm + SCR_OFF;
    int*   flg    = (int*)(sm + FLG_OFF);

    const int tid  = threadIdx.x;
    const int warp = tid >> 5;
    const int lane = tid & 31;
    const int gid  = lane >> 2;   // 0..7
    const int t4   = lane & 3;    // 0..3
    const int pair = warp & 3;    // 0..3
    const int role = warp >> 2;   // 0 or 1 (K half)
    const int r0   = blockIdx.x * 64;
    const int barid = 1 + pair;

    float* qout   = out;
    float* idxout = out + (size_t)N * DDIM + 5;

    // ---- A fragments for this warp's K half: 4 kk, 2x folded, tf32 hi/lo (32 regs) ----
    uint32_t a_hi[4][4], a_lo[4][4];
    {
        const float* p0 = x + (size_t)(r0 + pair * 16 + gid) * DDIM + role * 32 + t4;
        const float* p1 = p0 + 8 * DDIM;
#pragma unroll
        for (int kl = 0; kl < 4; kl++) {
            float xv[4] = { 2.f * p0[kl * 8], 2.f * p1[kl * 8],
                            2.f * p0[kl * 8 + 4], 2.f * p1[kl * 8 + 4] };
#pragma unroll
            for (int e = 0; e < 4; e++) {
                float hi = to_tf32(xv[e]);
                a_hi[kl][e] = __float_as_uint(hi);
                a_lo[kl][e] = __float_as_uint(to_tf32(xv[e] - hi));
            }
        }
    }

    // single softmax state per thread (role0: row pair*16+gid; role1: row pair*16+8+gid)
    float m0 = -1e30f, Z0 = 0.f, S0 = 0.f;
    int   b0i = 0;

    // staging: item v in [0,512) -> (code=v>>3, kk=v&7); thread owns v=tid, tid+256
    const int sc0 = tid >> 3, sk0 = tid & 7;
    const int sc1 = (tid + 256) >> 3, sk1 = (tid + 256) & 7;

    float4 pre[4];
    pre[0] = ((const float4*)emb)[(size_t)sc0 * 16 + sk0 * 2];
    pre[1] = ((const float4*)emb)[(size_t)sc0 * 16 + sk0 * 2 + 1];
    pre[2] = ((const float4*)emb)[(size_t)sc1 * 16 + sk1 * 2];
    pre[3] = ((const float4*)emb)[(size_t)sc1 * 16 + sk1 * 2 + 1];

    // per-thread exchange addresses: P[((pair*2+slot)*2+role)*64 + lane*2]
    float* pw0 = P + ((pair * 2 + 0) * 2 + role) * 64 + lane * 2;        // my write, slot 0
    float* pr0 = P + ((pair * 2 + 0) * 2 + (1 - role)) * 64 + lane * 2;  // my read,  slot 0
    const int pslotstride = 2 * 64;   // slot stride in floats

    for (int t = 0; t < CTILES; t++) {
        __syncthreads();
        // stage tile t into Es
#pragma unroll
        for (int i = 0; i < 2; i++) {
            float4 t0 = pre[2 * i], t1 = pre[2 * i + 1];
            int code = i ? sc1 : sc0, kk = i ? sk1 : sk0;
            float e[8] = { t0.x, t0.y, t0.z, t0.w, t1.x, t1.y, t1.z, t1.w };
            float hi[8], lo[8];
#pragma unroll
            for (int j = 0; j < 8; j++) { hi[j] = to_tf32(e[j]); lo[j] = to_tf32(e[j] - hi[j]); }
            float* base = Es + code * CSTRIDE + kk * KKSTRIDE;
#pragma unroll
            for (int q = 0; q < 4; q++)
                *(float4*)(base + q * 4) = make_float4(hi[q], hi[q + 4], lo[q], lo[q + 4]);
        }
        if (tid < 64) en2s[tid] = g_en2[t * 64 + tid];
        __syncthreads();
        // prefetch tile t+1 (overlaps MMA)
        if (t + 1 < CTILES) {
            int cb = (t + 1) * 64;
            pre[0] = ((const float4*)emb)[(size_t)(cb + sc0) * 16 + sk0 * 2];
            pre[1] = ((const float4*)emb)[(size_t)(cb + sc0) * 16 + sk0 * 2 + 1];
            pre[2] = ((const float4*)emb)[(size_t)(cb + sc1) * 16 + sk1 * 2];
            pre[3] = ((const float4*)emb)[(size_t)(cb + sc1) * 16 + sk1 * 2 + 1];
        }

#pragma unroll
        for (int ntl = 0; ntl < 8; ntl++) {
            float dA0 = 0.f, dA1 = 0.f, dA2 = 0.f, dA3 = 0.f;
            float dB0 = 0.f, dB1 = 0.f, dB2 = 0.f, dB3 = 0.f;
            const float* bp = Es + (ntl * 8 + gid) * CSTRIDE + (role * 4) * KKSTRIDE + t4 * 4;
#pragma unroll
            for (int kl = 0; kl < 4; kl++) {
                float4 f = *(const float4*)(bp + kl * KKSTRIDE);
                uint32_t hx = __float_as_uint(f.x), hy = __float_as_uint(f.y);
                uint32_t lx = __float_as_uint(f.z), ly = __float_as_uint(f.w);
                if ((kl & 1) == 0) {
                    mma_tf32(dA0, dA1, dA2, dA3, a_hi[kl], hx, hy);
                    mma_tf32(dB0, dB1, dB2, dB3, a_hi[kl], lx, ly);
                    mma_tf32(dA0, dA1, dA2, dA3, a_lo[kl], hx, hy);
                } else {
                    mma_tf32(dB0, dB1, dB2, dB3, a_hi[kl], hx, hy);
                    mma_tf32(dA0, dA1, dA2, dA3, a_hi[kl], lx, ly);
                    mma_tf32(dB0, dB1, dB2, dB3, a_lo[kl], hx, hy);
                }
            }
            float d0 = dA0 + dB0, d1 = dA1 + dB1;
            float d2 = dA2 + dB2, d3 = dA3 + dB3;

            // exchange: role0 hands off rows g+8 (d2,d3); role1 hands off rows g (d0,d1)
            int slot = (t * 8 + ntl) & 1;
            float* pw = pw0 + slot * pslotstride;
            const float* pr = pr0 + slot * pslotstride;
            if (role == 0) { pw[0] = d2; pw[1] = d3; }
            else           { pw[0] = d0; pw[1] = d1; }
            asm volatile("bar.sync %0, 64;" :: "r"(barid) : "memory");
            float o0 = pr[0], o1 = pr[1];

            int col0 = t * 64 + ntl * 8 + 2 * t4;
            float e20 = en2s[ntl * 8 + 2 * t4];
            float e21 = en2s[ntl * 8 + 2 * t4 + 1];
            float l0, l1;
            if (role == 0) { l0 = (d0 + o0) - e20; l1 = (d1 + o1) - e21; }
            else           { l0 = (d2 + o0) - e20; l1 = (d3 + o1) - e21; }
            UPD2(m0, Z0, S0, b0i, l0, l1, col0);
        }
    }

    // ---- merge the 4 column-threads of each row (shfl within quad) ----
#pragma unroll
    for (int off = 1; off <= 2; off <<= 1) {
        float m2 = __shfl_xor_sync(0xffffffffu, m0, off);
        float Z2 = __shfl_xor_sync(0xffffffffu, Z0, off);
        float S2 = __shfl_xor_sync(0xffffffffu, S0, off);
        int   b2 = __shfl_xor_sync(0xffffffffu, b0i, off);
        MERGE(m0, Z0, S0, b0i, m2, Z2, S2, b2);
    }
    if (t4 == 0) {
        int row = pair * 16 + role * 8 + gid;   // 0..63
        Rm[row] = m0; Rz[row] = Z0; Rs[row] = S0; RiA[row] = b0i;
    }
    __syncthreads();

    // ---- per-row entropy + index (64 rows) ----
    float H = 0.f;
    if (tid < 64) {
        float mm = Rm[tid], zz = Rz[tid], ss = Rs[tid];
        int ii = RiA[tid];
        H = mm + __logf(zz) - ss / zz;
        idxRow[tid] = ii;
        idxout[r0 + tid] = (float)ii;
        atomicAdd(&g_hist[ii], 1);
    }
    scr[tid] = (tid < 64) ? H : 0.f;
    __syncthreads();
    for (int s = 128; s > 0; s >>= 1) {
        if (tid < s) scr[tid] += scr[tid + s];
        __syncthreads();
    }
    if (tid == 0) g_pent[blockIdx.x] = scr[0];
    __syncthreads();

    // ---- gather quantized rows + commitment (64 rows x 16 float4 = 1024 items) ----
    float ca = 0.f;
#pragma unroll
    for (int i = 0; i < 4; i++) {
        int v = tid + 256 * i;
        int row = v >> 4;
        int c4 = v & 15;
        int code = idxRow[row];
        float4 q  = ((const float4*)emb)[(size_t)code * 16 + c4];
        float4 xv = ((const float4*)x)[(size_t)(r0 + row) * 16 + c4];
        ((float4*)qout)[(size_t)(r0 + row) * 16 + c4] = q;
        float dx = q.x - xv.x, dy = q.y - xv.y, dz = q.z - xv.z, dw = q.w - xv.w;
        ca += dx * dx + dy * dy + dz * dz + dw * dw;
    }
    __syncthreads();
    scr[tid] = ca;
    __syncthreads();
    for (int s = 128; s > 0; s >>= 1) {
        if (tid < s) scr[tid] += scr[tid + s];
        __syncthreads();
    }
    if (tid == 0) g_pcommit[blockIdx.x] = scr[0];

    // ---- last-block finalize (also restores the zero-invariant) ----
    __threadfence();
    if (tid == 0) {
        int tk = atomicAdd(&g_done, 1);
        *flg = (tk == NBLOCKS - 1) ? 1 : 0;
    }
    __syncthreads();
    if (*flg) {
        __threadfence();
        float v = 0.f;
        for (int i = tid; i < NBLOCKS; i += 256) v += g_pcommit[i];
        scr[tid] = v;
        __syncthreads();
        for (int s = 128; s > 0; s >>= 1) { if (tid < s) scr[tid] += scr[tid + s]; __syncthreads(); }
        float commitSum = scr[0];
        __syncthreads();

        v = 0.f;
        for (int i = tid; i < NBLOCKS; i += 256) v += g_pent[i];
        scr[tid] = v;
        __syncthreads();
        for (int s = 128; s > 0; s >>= 1) { if (tid < s) scr[tid] += scr[tid + s]; __syncthreads(); }
        float entSum = scr[0];
        __syncthreads();

        v = 0.f;
        for (int e = tid; e < 4096; e += 256) {
            float g = g_gram[e];
            v = fmaf(g, g, v);
            g_gram[e] = 0.f;                       // restore invariant
        }
        scr[tid] = v;
        __syncthreads();
        for (int s = 128; s > 0; s >>= 1) { if (tid < s) scr[tid] += scr[tid + s]; __syncthreads(); }
        float orthoSum = scr[0];
        __syncthreads();

        v = 0.f;
        for (int i = tid; i < KCODES; i += 256) {
            float avg = (float)g_hist[i] / (float)N;
            v += avg * logf(avg + 1e-10f);
            g_hist[i] = 0;                         // restore invariant
        }
        scr[tid] = v;
        __syncthreads();
        for (int s = 128; s > 0; s >>= 1) { if (tid < s) scr[tid] += scr[tid + s]; __syncthreads(); }
        float psum = scr[0];

        if (tid == 0) {
            size_t Q = (size_t)N * DDIM;
            float nu = 0.f;
            for (int i = 0; i < 16; i++) nu += g_usedp[i];
            out[Q + 0] = commitSum / (float)Q;                 // commitment_loss
            out[Q + 1] = orthoSum / (nu * nu) - 1.f / nu;      // ortho_loss
            out[Q + 2] = entSum / ((float)N * 10.f);           // entropy_loss (/log2(1024))
            out[Q + 3] = expf(-psum);                          // perplexity
            out[Q + 4] = nu / (float)KCODES;                   // coverage
            g_done = 0;                                        // restore invariant
        }
    }
}

extern "C" void kernel_launch(void* const* d_in, const int* in_sizes, int n_in,
                              void* d_out, int out_size) {
    const float* x   = (const float*)d_in[0];   // [16,2048,64] fp32
    const float* emb = (const float*)d_in[1];   // [1024,64] fp32
    const float* cc  = (const float*)d_in[2];   // [1024] fp32
    int N = in_sizes[0] / DDIM;                 // 32768

    cudaFuncSetAttribute(main_kernel, cudaFuncAttributeMaxDynamicSharedMemorySize, SMEM_BYTES);

    aux_kernel<<<16, 256>>>(emb, cc);
    main_kernel<<<NBLOCKS, 256, SMEM_BYTES>>>(x, emb, (float*)d_out, N);
}

// round 17
// speedup vs baseline: 1.5470x; 1.5470x over previous
#include <cuda_runtime.h>
#include <cuda_fp16.h>
#include <math.h>
#include <stdint.h>

#define KCODES 1024
#define DDIM   64
#define NBLOCKS 256       // 32768 rows / 128 rows per block
#define CTILES  16        // 1024 codes / 64 codes per tile

// ---------------- device scratch (no allocation allowed) ----------------
// g_hist, g_gram, g_done rely on the zero-invariant: zero at module load,
// re-zeroed by finalize at the end of every run (graph-replay safe).
__device__ float g_en2[KCODES];
__device__ int   g_hist[KCODES];
__device__ float g_usedp[16];
__device__ float g_pcommit[NBLOCKS];
__device__ float g_pent[NBLOCKS];
__device__ float g_gram[4096];
__device__ int   g_done;

// ---------------- helpers ----------------
// split v into fp16 hi + fp16 lo (v approx hi + lo, 22-bit effective)
__device__ __forceinline__ void pack2x(float v0, float v1, uint32_t& hi, uint32_t& lo) {
    __half h0 = __float2half_rn(v0);
    __half h1 = __float2half_rn(v1);
    float l0 = v0 - __half2float(h0);
    float l1 = v1 - __half2float(h1);
    __half2 hh = __halves2half2(h0, h1);
    __half2 ll = __halves2half2(__float2half_rn(l0), __float2half_rn(l1));
    hi = *(uint32_t*)&hh;
    lo = *(uint32_t*)&ll;
}

// D += A(m16k16 f16 row) * B(k16n8 f16 col), fp32 accum
__device__ __forceinline__ void mma_f16(float& d0, float& d1, float& d2, float& d3,
                                        const uint32_t a[4], uint32_t b0, uint32_t b1) {
    asm("mma.sync.aligned.m16n8k16.row.col.f32.f16.f16.f32 "
        "{%0,%1,%2,%3}, {%4,%5,%6,%7}, {%8,%9}, {%0,%1,%2,%3};"
        : "+f"(d0), "+f"(d1), "+f"(d2), "+f"(d3)
        : "r"(a[0]), "r"(a[1]), "r"(a[2]), "r"(a[3]), "r"(b0), "r"(b1));
}

#define UPD2(mv, Zv, Sv, biv, av0, av1, col0) do {                            \
    float _q = fmaxf((av0), (av1));                                           \
    if (_q > (mv)) {                                                          \
        float _scl = __expf((mv) - _q);                                       \
        (Zv) *= _scl; (Sv) *= _scl;                                           \
        (mv) = _q;                                                            \
        (biv) = ((av0) >= (av1)) ? (col0) : (col0) + 1;                       \
    }                                                                         \
    float _p0 = __expf((av0) - (mv));                                         \
    float _p1 = __expf((av1) - (mv));                                         \
    (Zv) += _p0 + _p1;                                                        \
    (Sv) = fmaf((av0), _p0, fmaf((av1), _p1, (Sv)));                          \
} while (0)

#define MERGE(mv, Zv, Sv, biv, m2, Z2, S2, b2) do {                           \
    float _mm = fmaxf((mv), (m2));                                            \
    float _sA = __expf((mv) - _mm);                                           \
    float _sB = __expf((m2) - _mm);                                           \
    float _Zn = (Zv) * _sA + (Z2) * _sB;                                      \
    float _Sn = (Sv) * _sA + (S2) * _sB;                                      \
    if ((m2) > (mv) || ((m2) == (mv) && (b2) < (biv))) (biv) = (b2);          \
    (mv) = _mm; (Zv) = _Zn; (Sv) = _Sn; } while (0)

// ---------------- aux: en2 + used + ortho Gram partial (16 blocks x 256) ----------------
__global__ __launch_bounds__(256, 4)
void aux_kernel(const float* __restrict__ emb, const float* __restrict__ cc) {
    __shared__ float nt[64 * 68];
    __shared__ float scl[64];
    int tid = threadIdx.x;
    int k0 = blockIdx.x * 64;

#pragma unroll
    for (int i = 0; i < 4; i++) {
        int v = tid + 256 * i;
        int k = v >> 4, c4 = v & 15;
        *(float4*)(nt + k * 68 + c4 * 4) = ((const float4*)emb)[(size_t)(k0 + k) * 16 + c4];
    }
    __syncthreads();

    if (tid < 64) {
        float s = 0.f;
        const float* r = nt + tid * 68;
#pragma unroll 8
        for (int d = 0; d < 64; d++) s = fmaf(r[d], r[d], s);
        g_en2[k0 + tid] = s;
        float msk = (cc[k0 + tid] >= 1.f) ? 1.f : 0.f;
        scl[tid] = msk / fmaxf(sqrtf(s), 1e-12f);
    }
    __syncthreads();

    if (tid == 0) {
        float u = 0.f;
        for (int i = 0; i < 64; i++) u += (scl[i] > 0.f) ? 1.f : 0.f;
        g_usedp[blockIdx.x] = u;
    }

#pragma unroll
    for (int i = 0; i < 4; i++) {
        int v = tid + 256 * i;
        int k = v >> 4, c4 = v & 15;
        float4* p = (float4*)(nt + k * 68 + c4 * 4);
        float4 t = *p;
        float s = scl[k];
        t.x *= s; t.y *= s; t.z *= s; t.w *= s;
        *p = t;
    }
    __syncthreads();

    int a = tid >> 2;
    int bg = tid & 3;
    float acc[16];
#pragma unroll
    for (int i = 0; i < 16; i++) acc[i] = 0.f;
#pragma unroll 4
    for (int k = 0; k < 64; k++) {
        float va = nt[k * 68 + a];
        const float4* bp = (const float4*)(nt + k * 68 + bg * 16);
        float4 q0 = bp[0], q1 = bp[1], q2 = bp[2], q3 = bp[3];
        acc[0]  = fmaf(va, q0.x, acc[0]);  acc[1]  = fmaf(va, q0.y, acc[1]);
        acc[2]  = fmaf(va, q0.z, acc[2]);  acc[3]  = fmaf(va, q0.w, acc[3]);
        acc[4]  = fmaf(va, q1.x, acc[4]);  acc[5]  = fmaf(va, q1.y, acc[5]);
        acc[6]  = fmaf(va, q1.z, acc[6]);  acc[7]  = fmaf(va, q1.w, acc[7]);
        acc[8]  = fmaf(va, q2.x, acc[8]);  acc[9]  = fmaf(va, q2.y, acc[9]);
        acc[10] = fmaf(va, q2.z, acc[10]); acc[11] = fmaf(va, q2.w, acc[11]);
        acc[12] = fmaf(va, q3.x, acc[12]); acc[13] = fmaf(va, q3.y, acc[13]);
        acc[14] = fmaf(va, q3.z, acc[14]); acc[15] = fmaf(va, q3.w, acc[15]);
    }
    float* op = g_gram + a * 64 + bg * 16;
#pragma unroll
    for (int i = 0; i < 16; i++) atomicAdd(op + i, acc[i]);
}

// ---------------- main: fp16 split-pair m16n8k16 3-term GEMM + fused softmax/argmax ----------------
// B smem: EsBuf[b][code*20 + chunk*4 + t4] = uint4 {hi_b0, hi_b1, lo_b0, lo_b1}
//   b0 = half2(e[c*16+2t4], e[c*16+2t4+1]), b1 = half2(e[c*16+2t4+8], e[c*16+2t4+9])
// code stride 20 quads = 320 B -> conflict-free for both staging STS.128 and mainloop LDS.128.
__global__ __launch_bounds__(256, 3)
void main_kernel(const float* __restrict__ x, const float* __restrict__ emb,
                 float* __restrict__ out, int N) {
    __shared__ uint4 EsBuf[2][64 * 20];          // 2 x 20480 B
    __shared__ float en2s[2][64];
    __shared__ float Rm[128], Rz[128], Rs[128];
    __shared__ int   RiA[128], idxRow[128];
    __shared__ float scr[256];
    __shared__ int   flg;

    const int tid  = threadIdx.x;
    const int warp = tid >> 5;
    const int lane = tid & 31;
    const int gid  = lane >> 2;   // 0..7
    const int t4   = lane & 3;    // 0..3
    const int r0   = blockIdx.x * 128;

    float* qout   = out;
    float* idxout = out + (size_t)N * DDIM + 5;

    // ---- A fragments: rows warp*16+gid (+8), 2x folded, fp16 hi/lo split (32 regs) ----
    uint32_t a_hi[4][4], a_lo[4][4];
    {
        const float* xr0 = x + (size_t)(r0 + warp * 16 + gid) * DDIM;
        const float* xr1 = xr0 + 8 * DDIM;
#pragma unroll
        for (int c = 0; c < 4; c++) {
            float2 p00 = *(const float2*)(xr0 + c * 16 + 2 * t4);
            float2 p01 = *(const float2*)(xr0 + c * 16 + 2 * t4 + 8);
            float2 p10 = *(const float2*)(xr1 + c * 16 + 2 * t4);
            float2 p11 = *(const float2*)(xr1 + c * 16 + 2 * t4 + 8);
            pack2x(2.f * p00.x, 2.f * p00.y, a_hi[c][0], a_lo[c][0]);
            pack2x(2.f * p10.x, 2.f * p10.y, a_hi[c][1], a_lo[c][1]);
            pack2x(2.f * p01.x, 2.f * p01.y, a_hi[c][2], a_lo[c][2]);
            pack2x(2.f * p11.x, 2.f * p11.y, a_hi[c][3], a_lo[c][3]);
        }
    }

    float m0 = -1e30f, Z0 = 0.f, S0 = 0.f;
    float m1 = -1e30f, Z1 = 0.f, S1 = 0.f;
    int   b0i = 0, b1i = 0;

    // staging item: thread -> (code = tid>>2, t4v = tid&3); loops 4 chunks
    const int sco = tid >> 2, st4 = tid & 3;

    // prefetch tile 0: 8 float2 per thread
    float2 pre[8];
    {
        const float* er = emb + (size_t)sco * DDIM;
#pragma unroll
        for (int c = 0; c < 4; c++) {
            pre[2 * c]     = *(const float2*)(er + c * 16 + 2 * st4);
            pre[2 * c + 1] = *(const float2*)(er + c * 16 + 2 * st4 + 8);
        }
    }
    // stage tile 0 into buffer 0
#pragma unroll
    for (int c = 0; c < 4; c++) {
        uint32_t h0, l0, h1, l1;
        pack2x(pre[2 * c].x, pre[2 * c].y, h0, l0);
        pack2x(pre[2 * c + 1].x, pre[2 * c + 1].y, h1, l1);
        EsBuf[0][sco * 20 + c * 4 + st4] = make_uint4(h0, h1, l0, l1);
    }
    if (tid < 64) en2s[0][tid] = g_en2[tid];
    // prefetch tile 1
    {
        const float* er = emb + (size_t)(64 + sco) * DDIM;
#pragma unroll
        for (int c = 0; c < 4; c++) {
            pre[2 * c]     = *(const float2*)(er + c * 16 + 2 * st4);
            pre[2 * c + 1] = *(const float2*)(er + c * 16 + 2 * st4 + 8);
        }
    }
    __syncthreads();

    for (int t = 0; t < CTILES; t++) {
        // stage tile t+1 into the other buffer (overlaps MMA of tile t)
        if (t + 1 < CTILES) {
            int nb = (t + 1) & 1;
#pragma unroll
            for (int c = 0; c < 4; c++) {
                uint32_t h0, l0, h1, l1;
                pack2x(pre[2 * c].x, pre[2 * c].y, h0, l0);
                pack2x(pre[2 * c + 1].x, pre[2 * c + 1].y, h1, l1);
                EsBuf[nb][sco * 20 + c * 4 + st4] = make_uint4(h0, h1, l0, l1);
            }
            if (tid < 64) en2s[nb][tid] = g_en2[(t + 1) * 64 + tid];
            if (t + 2 < CTILES) {
                const float* er = emb + (size_t)((t + 2) * 64 + sco) * DDIM;
#pragma unroll
                for (int c = 0; c < 4; c++) {
                    pre[2 * c]     = *(const float2*)(er + c * 16 + 2 * st4);
                    pre[2 * c + 1] = *(const float2*)(er + c * 16 + 2 * st4 + 8);
                }
            }
        }

        // MMA + epilogue on tile t
        const uint4* Es = EsBuf[t & 1];
        const float* ens = en2s[t & 1];
#pragma unroll
        for (int ntl = 0; ntl < 8; ntl++) {
            float dA0 = 0.f, dA1 = 0.f, dA2 = 0.f, dA3 = 0.f;
            float dB0 = 0.f, dB1 = 0.f, dB2 = 0.f, dB3 = 0.f;
            const uint4* bp = Es + (ntl * 8 + gid) * 20 + t4;
#pragma unroll
            for (int c = 0; c < 4; c++) {
                uint4 q = bp[c * 4];
                if ((c & 1) == 0) {
                    mma_f16(dA0, dA1, dA2, dA3, a_hi[c], q.x, q.y);
                    mma_f16(dB0, dB1, dB2, dB3, a_hi[c], q.z, q.w);
                    mma_f16(dA0, dA1, dA2, dA3, a_lo[c], q.x, q.y);
                } else {
                    mma_f16(dB0, dB1, dB2, dB3, a_hi[c], q.x, q.y);
                    mma_f16(dA0, dA1, dA2, dA3, a_hi[c], q.z, q.w);
                    mma_f16(dB0, dB1, dB2, dB3, a_lo[c], q.x, q.y);
                }
            }
            float d0 = dA0 + dB0, d1 = dA1 + dB1;
            float d2 = dA2 + dB2, d3 = dA3 + dB3;
            int col0 = t * 64 + ntl * 8 + 2 * t4;
            float e20 = ens[ntl * 8 + 2 * t4];
            float e21 = ens[ntl * 8 + 2 * t4 + 1];
            float av0 = d0 - e20, av1 = d1 - e21;
            float av2 = d2 - e20, av3 = d3 - e21;
            UPD2(m0, Z0, S0, b0i, av0, av1, col0);
            UPD2(m1, Z1, S1, b1i, av2, av3, col0);
        }
        __syncthreads();
    }

    // ---- merge the 4 column-threads of each row (shfl within quad) ----
#pragma unroll
    for (int off = 1; off <= 2; off <<= 1) {
        float m2 = __shfl_xor_sync(0xffffffffu, m0, off);
        float Z2 = __shfl_xor_sync(0xffffffffu, Z0, off);
        float S2 = __shfl_xor_sync(0xffffffffu, S0, off);
        int   b2 = __shfl_xor_sync(0xffffffffu, b0i, off);
        MERGE(m0, Z0, S0, b0i, m2, Z2, S2, b2);
        float m3 = __shfl_xor_sync(0xffffffffu, m1, off);
        float Z3 = __shfl_xor_sync(0xffffffffu, Z1, off);
        float S3 = __shfl_xor_sync(0xffffffffu, S1, off);
        int   b3 = __shfl_xor_sync(0xffffffffu, b1i, off);
        MERGE(m1, Z1, S1, b1i, m3, Z3, S3, b3);
    }
    if (t4 == 0) {
        int rowA = warp * 16 + gid;
        Rm[rowA] = m0; Rz[rowA] = Z0; Rs[rowA] = S0; RiA[rowA] = b0i;
        Rm[rowA + 8] = m1; Rz[rowA + 8] = Z1; Rs[rowA + 8] = S1; RiA[rowA + 8] = b1i;
    }
    __syncthreads();

    // ---- per-row entropy + index ----
    float H = 0.f;
    if (tid < 128) {
        float mm = Rm[tid], zz = Rz[tid], ss = Rs[tid];
        int ii = RiA[tid];
        H = mm + __logf(zz) - ss / zz;
        idxRow[tid] = ii;
        idxout[r0 + tid] = (float)ii;
        atomicAdd(&g_hist[ii], 1);
    }
    scr[tid] = (tid < 128) ? H : 0.f;
    __syncthreads();
    for (int s = 128; s > 0; s >>= 1) {
        if (tid < s) scr[tid] += scr[tid + s];
        __syncthreads();
    }
    if (tid == 0) g_pent[blockIdx.x] = scr[0];
    __syncthreads();

    // ---- gather quantized rows + commitment ----
    float ca = 0.f;
#pragma unroll
    for (int i = 0; i < 8; i++) {
        int v = tid + 256 * i;
        int row = v >> 4;
        int c4 = v & 15;
        int code = idxRow[row];
        float4 q  = ((const float4*)emb)[(size_t)code * 16 + c4];
        float4 xv = ((const float4*)x)[(size_t)(r0 + row) * 16 + c4];
        ((float4*)qout)[(size_t)(r0 + row) * 16 + c4] = q;
        float dx = q.x - xv.x, dy = q.y - xv.y, dz = q.z - xv.z, dw = q.w - xv.w;
        ca += dx * dx + dy * dy + dz * dz + dw * dw;
    }
    __syncthreads();
    scr[tid] = ca;
    __syncthreads();
    for (int s = 128; s > 0; s >>= 1) {
        if (tid < s) scr[tid] += scr[tid + s];
        __syncthreads();
    }
    if (tid == 0) g_pcommit[blockIdx.x] = scr[0];

    // ---- last-block finalize (also restores the zero-invariant) ----
    __threadfence();
    if (tid == 0) {
        int tk = atomicAdd(&g_done, 1);
        flg = (tk == NBLOCKS - 1) ? 1 : 0;
    }
    __syncthreads();
    if (flg) {
        __threadfence();
        float v = 0.f;
        for (int i = tid; i < NBLOCKS; i += 256) v += g_pcommit[i];
        scr[tid] = v;
        __syncthreads();
        for (int s = 128; s > 0; s >>= 1) { if (tid < s) scr[tid] += scr[tid + s]; __syncthreads(); }
        float commitSum = scr[0];
        __syncthreads();

        v = 0.f;
        for (int i = tid; i < NBLOCKS; i += 256) v += g_pent[i];
        scr[tid] = v;
        __syncthreads();
        for (int s = 128; s > 0; s >>= 1) { if (tid < s) scr[tid] += scr[tid + s]; __syncthreads(); }
        float entSum = scr[0];
        __syncthreads();

        v = 0.f;
        for (int e = tid; e < 4096; e += 256) {
            float g = g_gram[e];
            v = fmaf(g, g, v);
            g_gram[e] = 0.f;                       // restore invariant
        }
        scr[tid] = v;
        __syncthreads();
        for (int s = 128; s > 0; s >>= 1) { if (tid < s) scr[tid] += scr[tid + s]; __syncthreads(); }
        float orthoSum = scr[0];
        __syncthreads();

        v = 0.f;
        for (int i = tid; i < KCODES; i += 256) {
            float avg = (float)g_hist[i] / (float)N;
            v += avg * logf(avg + 1e-10f);
            g_hist[i] = 0;                         // restore invariant
        }
        scr[tid] = v;
        __syncthreads();
        for (int s = 128; s > 0; s >>= 1) { if (tid < s) scr[tid] += scr[tid + s]; __syncthreads(); }
        float psum = scr[0];

        if (tid == 0) {
            size_t Q = (size_t)N * DDIM;
            float nu = 0.f;
            for (int i = 0; i < 16; i++) nu += g_usedp[i];
            out[Q + 0] = commitSum / (float)Q;                 // commitment_loss
            out[Q + 1] = orthoSum / (nu * nu) - 1.f / nu;      // ortho_loss
            out[Q + 2] = entSum / ((float)N * 10.f);           // entropy_loss (/log2(1024))
            out[Q + 3] = expf(-psum);                          // perplexity
            out[Q + 4] = nu / (float)KCODES;                   // coverage
            g_done = 0;                                        // restore invariant
        }
    }
}

extern "C" void kernel_launch(void* const* d_in, const int* in_sizes, int n_in,
                              void* d_out, int out_size) {
    const float* x   = (const float*)d_in[0];   // [16,2048,64] fp32
    const float* emb = (const float*)d_in[1];   // [1024,64] fp32
    const float* cc  = (const float*)d_in[2];   // [1024] fp32
    int N = in_sizes[0] / DDIM;                 // 32768

    aux_kernel<<<16, 256>>>(emb, cc);
    main_kernel<<<NBLOCKS, 256>>>(x, emb, (float*)d_out, N);
}